// round 4
// baseline (speedup 1.0000x reference)
#include <cuda_runtime.h>
#include <math.h>

#define FULL 0xffffffffu

// Global-reduction scratch (graph-replay safe: re-zeroed by k_zero each launch)
__device__ double g_sum0, g_sum1;
__device__ int    g_cnt;

__global__ void k_zero() { g_sum0 = 0.0; g_sum1 = 0.0; g_cnt = 0; }

// Pass 1: per-ray sphere intersection, reduce sum(si0), sum(si1), count over hits
__global__ __launch_bounds__(256) void k_reduce(const float* __restrict__ rd,
                                                const float* __restrict__ cam, int P) {
    int i = blockIdx.x * blockDim.x + threadIdx.x;
    float cx = cam[0], cy = cam[1], cz = cam[2];
    float c2 = cx * cx + cy * cy + cz * cz - 1.0f;  // R_SPHERE = 1
    float s0 = 0.f, s1 = 0.f; int c = 0;
    if (i < P) {
        float x = rd[3 * i + 0], y = rd[3 * i + 1], z = rd[3 * i + 2];
        float dt = x * cx + y * cy + z * cz;
        float un = dt * dt - c2;
        if (un > 0.f) {
            float sq = sqrtf(un);
            s0 = -sq - dt; s1 = sq - dt; c = 1;
        }
    }
    // warp reduce
    #pragma unroll
    for (int d = 16; d; d >>= 1) {
        s0 += __shfl_down_sync(FULL, s0, d);
        s1 += __shfl_down_sync(FULL, s1, d);
        c  += __shfl_down_sync(FULL, c, d);
    }
    __shared__ float sh0[8], sh1[8]; __shared__ int shc[8];
    int w = threadIdx.x >> 5, ln = threadIdx.x & 31;
    if (ln == 0) { sh0[w] = s0; sh1[w] = s1; shc[w] = c; }
    __syncthreads();
    if (threadIdx.x == 0) {
        float a0 = 0.f, a1 = 0.f; int ac = 0;
        #pragma unroll
        for (int j = 0; j < 8; j++) { a0 += sh0[j]; a1 += sh1[j]; ac += shc[j]; }
        atomicAdd(&g_sum0, (double)a0);
        atomicAdd(&g_sum1, (double)a1);
        atomicAdd(&g_cnt, ac);
    }
}

// shuffle gather from a 64-entry per-warp array stored 2 values/lane (v0=idx 2l, v1=idx 2l+1)
__device__ __forceinline__ float gat(float v0, float v1, int k) {
    float a = __shfl_sync(FULL, v0, k >> 1);
    float b = __shfl_sync(FULL, v1, k >> 1);
    return (k & 1) ? b : a;
}

// Pass 2: one warp per ray. Lane l owns steps {2l, 2l+1}.
__global__ __launch_bounds__(256) void k_main(const float* __restrict__ rd,
                                              const float* __restrict__ cam,
                                              const float* __restrict__ trand,
                                              float* __restrict__ ns,
                                              float* __restrict__ zs,
                                              float* __restrict__ wout, int P) {
    int gt   = blockIdx.x * blockDim.x + threadIdx.x;
    int ray  = gt >> 5;
    int lane = gt & 31;
    if (ray >= P) return;   // whole warp together (P is warp-granular)

    float cx = cam[0], cy = cam[1], cz = cam[2];
    float c2 = cx * cx + cy * cy + cz * cz - 1.0f;
    float x = rd[3 * ray + 0], y = rd[3 * ray + 1], z = rd[3 * ray + 2];
    float dt = x * cx + y * cy + z * cz;
    float un = dt * dt - c2;

    float si0, si1;
    if (un > 0.f) {
        float sq = sqrtf(un);
        si0 = -sq - dt; si1 = sq - dt;
    } else {
        int nh = max(g_cnt, 1);
        si0 = (float)(g_sum0 / (double)nh);
        si1 = (float)(g_sum1 / (double)nh);
    }
    si0 = fmaxf(si0, 0.f); si1 = fmaxf(si1, 0.f);
    float mind = si0;
    float rng  = si1 - si0;
    float sd   = rng * (1.0f / 64.0f);

    // steps (coalesced float2 load of t_rand)
    float2 tr = *(const float2*)(trand + (size_t)ray * 64 + 2 * lane);
    int i0 = 2 * lane, i1 = 2 * lane + 1;
    float st0 = mind + ((float)i0 * (1.0f / 63.0f)) * rng + (tr.x - 0.5f) * sd;
    float st1 = mind + ((float)i1 * (1.0f / 63.0f)) * rng + (tr.y - 0.5f) * sd;

    // SDF at both steps
    float px = cx + st0 * x, py = cy + st0 * y, pz = cz + st0 * z;
    float s_0 = sqrtf(px * px + py * py + pz * pz) - 0.5f;
    px = cx + st1 * x; py = cy + st1 * y; pz = cz + st1 * z;
    float s_1 = sqrtf(px * px + py * py + pz * pz) - 0.5f;

    const float inv_s = 20.085536923187668f;  // exp(0.3 * 10)
    float sg0 = 1.0f / (1.0f + __expf(-s_0 * inv_s));
    float sg1 = 1.0f / (1.0f + __expf(-s_1 * inv_s));
    float sgn = __shfl_down_sync(FULL, sg0, 1);   // sigmoid(sdf[2l+2]) from next lane

    float a0 = fminf(fmaxf((sg0 - sg1 + 1e-8f) / (sg0 + 1e-8f), 0.f), 1.f);
    float a1 = (lane < 31)
             ? fminf(fmaxf((sg1 - sgn + 1e-8f) / (sg1 + 1e-8f), 0.f), 1.f)
             : 0.f;

    float g0 = 1.0f - a0 + 1e-7f;
    float g1 = (lane < 31) ? (1.0f - a1 + 1e-7f) : 1.0f;

    // exclusive prefix-product across warp of per-lane pair product
    float p  = g0 * g1;
    float pi = p;
    #pragma unroll
    for (int d = 1; d < 32; d <<= 1) {
        float v = __shfl_up_sync(FULL, pi, d);
        if (lane >= d) pi *= v;
    }
    float Pex = __shfl_up_sync(FULL, pi, 1);
    if (lane == 0) Pex = 1.0f;

    float w0 = a0 * Pex;            // weights[2l]
    float w1 = a1 * (Pex * g0);     // weights[2l+1] (invalid/unused for lane 31)

    // unnormalized CDF (cumsum of w + 1e-8); index 63 padded with 0 contribution
    float e0 = w0 + 1e-8f;
    float e1 = (lane < 31) ? (w1 + 1e-8f) : 0.f;
    float q  = e0 + e1;
    float qi = q;
    #pragma unroll
    for (int d = 1; d < 32; d <<= 1) {
        float v = __shfl_up_sync(FULL, qi, d);
        if (lane >= d) qi += v;
    }
    float Sex = __shfl_up_sync(FULL, qi, 1);
    if (lane == 0) Sex = 0.f;
    float cum0  = Sex + e0;   // cumw[2l]
    float cum1  = qi;         // cumw[2l+1]
    float total = __shfl_sync(FULL, qi, 31);

    // write weights (63 per ray, contiguous per warp)
    size_t wbase = (size_t)ray * 63;
    wout[wbase + i0] = w0;
    if (lane < 31) wout[wbase + i1] = w1;

    // importance sample: one u per lane, u = (2l+1)/64
    float u  = (float)(2 * lane + 1) * (1.0f / 64.0f);
    float uT = u * total;

    // c = count of cumw[k] <= uT over k in [0,63)  (binary search via shuffle gather)
    int c = 0;
    #pragma unroll
    for (int s = 32; s; s >>= 1) {
        int k  = c + s - 1;
        int kk = min(k, 63);
        float v = gat(cum0, cum1, kk);
        if (k < 63 && v <= uT) c += s;
    }
    // inds = c+1; below = c; above = min(c+1, 63)
    int   ab   = min(c + 1, 63);
    float rtot = 1.0f / total;
    float cdfb = (c == 0) ? 0.f : gat(cum0, cum1, c - 1) * rtot;
    float cdfa = gat(cum0, cum1, ab - 1) * rtot;
    float binb = gat(st0, st1, c);
    float bina = gat(st0, st1, ab);
    float den  = cdfa - cdfb;
    den = (den < 1e-8f) ? 1.0f : den;
    float zv = binb + ((u - cdfb) / den) * (bina - binb);

    // outputs: z_samples (coalesced), new_samples (contiguous 384B per warp)
    zs[(size_t)ray * 32 + lane] = zv;
    size_t nb = (size_t)ray * 96 + (size_t)lane * 3;
    ns[nb + 0] = cx + zv * x;
    ns[nb + 1] = cy + zv * y;
    ns[nb + 2] = cz + zv * z;
}

extern "C" void kernel_launch(void* const* d_in, const int* in_sizes, int n_in,
                              void* d_out, int out_size) {
    const float* rd  = (const float*)d_in[0];   // ray_dirs (1, P, 3)
    const float* cam = (const float*)d_in[1];   // cam_loc (1, 3)
    const float* tr  = (const float*)d_in[2];   // t_rand (P, 64)
    int P = in_sizes[0] / 3;

    float* out = (float*)d_out;
    float* ns  = out;                                     // (P, 32, 3)
    float* zs  = out + (size_t)P * 96;                    // (P, 32)
    float* wo  = out + (size_t)P * 96 + (size_t)P * 32;   // (P, 63)

    k_zero<<<1, 1>>>();
    k_reduce<<<(P + 255) / 256, 256>>>(rd, cam, P);
    long long tot = (long long)P * 32;
    k_main<<<(int)((tot + 255) / 256), 256>>>(rd, cam, tr, ns, zs, wo, P);
}

// round 5
// speedup vs baseline: 3.9437x; 3.9437x over previous
#include <cuda_runtime.h>
#include <math.h>

#define FULL 0xffffffffu

// Global-reduction scratch (graph-replay safe: re-zeroed by k_zero each launch)
__device__ double g_sum0, g_sum1;
__device__ int    g_cnt;
__device__ int    g_done;
__device__ float  g_mean0, g_mean1;   // finalized means (float — no FP64 in hot kernel)

__global__ void k_zero() {
    g_sum0 = 0.0; g_sum1 = 0.0; g_cnt = 0; g_done = 0;
    g_mean0 = 0.f; g_mean1 = 0.f;
}

// Pass 1: per-ray sphere intersection; reduce sum(si0), sum(si1), count over hits.
// Last block finalizes the means so k_main never touches FP64.
__global__ __launch_bounds__(256) void k_reduce(const float* __restrict__ rd,
                                                const float* __restrict__ cam, int P) {
    int i = blockIdx.x * blockDim.x + threadIdx.x;
    float cx = cam[0], cy = cam[1], cz = cam[2];
    float c2 = cx * cx + cy * cy + cz * cz - 1.0f;  // R_SPHERE = 1
    float s0 = 0.f, s1 = 0.f; int c = 0;
    if (i < P) {
        float x = rd[3 * i + 0], y = rd[3 * i + 1], z = rd[3 * i + 2];
        float dt = x * cx + y * cy + z * cz;
        float un = dt * dt - c2;
        if (un > 0.f) {
            float sq = sqrtf(un);
            s0 = -sq - dt; s1 = sq - dt; c = 1;
        }
    }
    #pragma unroll
    for (int d = 16; d; d >>= 1) {
        s0 += __shfl_down_sync(FULL, s0, d);
        s1 += __shfl_down_sync(FULL, s1, d);
        c  += __shfl_down_sync(FULL, c, d);
    }
    __shared__ float sh0[8], sh1[8]; __shared__ int shc[8];
    int w = threadIdx.x >> 5, ln = threadIdx.x & 31;
    if (ln == 0) { sh0[w] = s0; sh1[w] = s1; shc[w] = c; }
    __syncthreads();
    if (threadIdx.x == 0) {
        float a0 = 0.f, a1 = 0.f; int ac = 0;
        #pragma unroll
        for (int j = 0; j < 8; j++) { a0 += sh0[j]; a1 += sh1[j]; ac += shc[j]; }
        atomicAdd(&g_sum0, (double)a0);
        atomicAdd(&g_sum1, (double)a1);
        atomicAdd(&g_cnt, ac);
        __threadfence();
        int t = atomicAdd(&g_done, 1);
        if (t == (int)gridDim.x - 1) {
            // read via atomic to guarantee L2-coherent values
            double t0 = atomicAdd(&g_sum0, 0.0);
            double t1 = atomicAdd(&g_sum1, 0.0);
            int    nc = atomicAdd(&g_cnt, 0);
            int nh = nc > 0 ? nc : 1;
            g_mean0 = (float)(t0 / (double)nh);   // one FP64 divide per launch
            g_mean1 = (float)(t1 / (double)nh);
        }
    }
}

// shuffle gather from a 64-entry per-warp array stored 2 values/lane (v0=idx 2l, v1=idx 2l+1)
__device__ __forceinline__ float gat(float v0, float v1, int k) {
    float a = __shfl_sync(FULL, v0, k >> 1);
    float b = __shfl_sync(FULL, v1, k >> 1);
    return (k & 1) ? b : a;
}

// Pass 2: one warp per ray. Lane l owns steps {2l, 2l+1}.
__global__ __launch_bounds__(256) void k_main(const float* __restrict__ rd,
                                              const float* __restrict__ cam,
                                              const float* __restrict__ trand,
                                              float* __restrict__ ns,
                                              float* __restrict__ zs,
                                              float* __restrict__ wout, int P) {
    int gt   = blockIdx.x * blockDim.x + threadIdx.x;
    int ray  = gt >> 5;
    int lane = gt & 31;
    if (ray >= P) return;

    float cx = cam[0], cy = cam[1], cz = cam[2];
    float c2 = cx * cx + cy * cy + cz * cz - 1.0f;
    float x = rd[3 * ray + 0], y = rd[3 * ray + 1], z = rd[3 * ray + 2];
    float dt = x * cx + y * cy + z * cz;
    float un = dt * dt - c2;

    float si0, si1;
    if (un > 0.f) {
        float sq = sqrtf(un);
        si0 = -sq - dt; si1 = sq - dt;
    } else {
        si0 = g_mean0;
        si1 = g_mean1;
    }
    si0 = fmaxf(si0, 0.f); si1 = fmaxf(si1, 0.f);
    float mind = si0;
    float rng  = si1 - si0;
    float sd   = rng * (1.0f / 64.0f);

    // steps (coalesced float2 load of t_rand)
    float2 tr = *(const float2*)(trand + (size_t)ray * 64 + 2 * lane);
    int i0 = 2 * lane, i1 = 2 * lane + 1;
    float st0 = mind + ((float)i0 * (1.0f / 63.0f)) * rng + (tr.x - 0.5f) * sd;
    float st1 = mind + ((float)i1 * (1.0f / 63.0f)) * rng + (tr.y - 0.5f) * sd;

    // SDF at both steps
    float px = cx + st0 * x, py = cy + st0 * y, pz = cz + st0 * z;
    float s_0 = sqrtf(px * px + py * py + pz * pz) - 0.5f;
    px = cx + st1 * x; py = cy + st1 * y; pz = cz + st1 * z;
    float s_1 = sqrtf(px * px + py * py + pz * pz) - 0.5f;

    const float inv_s = 20.085536923187668f;  // exp(0.3 * 10)
    float sg0 = 1.0f / (1.0f + __expf(-s_0 * inv_s));
    float sg1 = 1.0f / (1.0f + __expf(-s_1 * inv_s));
    float sgn = __shfl_down_sync(FULL, sg0, 1);   // sigmoid(sdf[2l+2]) from next lane

    float a0 = fminf(fmaxf(__fdividef(sg0 - sg1 + 1e-8f, sg0 + 1e-8f), 0.f), 1.f);
    float a1 = (lane < 31)
             ? fminf(fmaxf(__fdividef(sg1 - sgn + 1e-8f, sg1 + 1e-8f), 0.f), 1.f)
             : 0.f;

    float g0 = 1.0f - a0 + 1e-7f;
    float g1 = (lane < 31) ? (1.0f - a1 + 1e-7f) : 1.0f;

    // exclusive prefix-product across warp of per-lane pair product
    float p  = g0 * g1;
    float pi = p;
    #pragma unroll
    for (int d = 1; d < 32; d <<= 1) {
        float v = __shfl_up_sync(FULL, pi, d);
        if (lane >= d) pi *= v;
    }
    float Pex = __shfl_up_sync(FULL, pi, 1);
    if (lane == 0) Pex = 1.0f;

    float w0 = a0 * Pex;            // weights[2l]
    float w1 = a1 * (Pex * g0);     // weights[2l+1] (unused for lane 31)

    // unnormalized CDF (cumsum of w + 1e-8); index 63 padded with 0 contribution
    float e0 = w0 + 1e-8f;
    float e1 = (lane < 31) ? (w1 + 1e-8f) : 0.f;
    float q  = e0 + e1;
    float qi = q;
    #pragma unroll
    for (int d = 1; d < 32; d <<= 1) {
        float v = __shfl_up_sync(FULL, qi, d);
        if (lane >= d) qi += v;
    }
    float Sex = __shfl_up_sync(FULL, qi, 1);
    if (lane == 0) Sex = 0.f;
    float cum0  = Sex + e0;   // cumw[2l]
    float cum1  = qi;         // cumw[2l+1]
    float total = __shfl_sync(FULL, qi, 31);

    // write weights (63 per ray, contiguous per warp)
    size_t wbase = (size_t)ray * 63;
    wout[wbase + i0] = w0;
    if (lane < 31) wout[wbase + i1] = w1;

    // importance sample: one u per lane, u = (2l+1)/64
    float u  = (float)(2 * lane + 1) * (1.0f / 64.0f);
    float uT = u * total;

    // c = count of cumw[k] <= uT over k in [0,63)  (binary search via shuffle gather)
    int c = 0;
    #pragma unroll
    for (int s = 32; s; s >>= 1) {
        int k  = c + s - 1;
        int kk = min(k, 63);
        float v = gat(cum0, cum1, kk);
        if (k < 63 && v <= uT) c += s;
    }
    // inds = c+1; below = c; above = min(c+1, 63)
    int   ab   = min(c + 1, 63);
    float rtot = __frcp_rn(total);
    float cdfb = (c == 0) ? 0.f : gat(cum0, cum1, c - 1) * rtot;
    float cdfa = gat(cum0, cum1, ab - 1) * rtot;
    float binb = gat(st0, st1, c);
    float bina = gat(st0, st1, ab);
    float den  = cdfa - cdfb;
    den = (den < 1e-8f) ? 1.0f : den;
    float zv = binb + __fdividef(u - cdfb, den) * (bina - binb);

    // outputs: z_samples (coalesced), new_samples (contiguous 384B per warp)
    zs[(size_t)ray * 32 + lane] = zv;
    size_t nb = (size_t)ray * 96 + (size_t)lane * 3;
    ns[nb + 0] = cx + zv * x;
    ns[nb + 1] = cy + zv * y;
    ns[nb + 2] = cz + zv * z;
}

extern "C" void kernel_launch(void* const* d_in, const int* in_sizes, int n_in,
                              void* d_out, int out_size) {
    const float* rd  = (const float*)d_in[0];   // ray_dirs (1, P, 3)
    const float* cam = (const float*)d_in[1];   // cam_loc (1, 3)
    const float* tr  = (const float*)d_in[2];   // t_rand (P, 64)
    int P = in_sizes[0] / 3;

    float* out = (float*)d_out;
    float* ns  = out;                                     // (P, 32, 3)
    float* zs  = out + (size_t)P * 96;                    // (P, 32)
    float* wo  = out + (size_t)P * 96 + (size_t)P * 32;   // (P, 63)

    k_zero<<<1, 1>>>();
    k_reduce<<<(P + 255) / 256, 256>>>(rd, cam, P);
    long long tot = (long long)P * 32;
    k_main<<<(int)((tot + 255) / 256), 256>>>(rd, cam, tr, ns, zs, wo, P);
}

// round 6
// speedup vs baseline: 5.5175x; 1.3991x over previous
#include <cuda_runtime.h>
#include <math.h>

#define FULL 0xffffffffu

// Global-reduction scratch. Statically zero; the k_reduce finalizer resets it
// after use so every graph replay sees the same initial state (no k_zero launch).
__device__ double g_sum0 = 0.0, g_sum1 = 0.0;
__device__ int    g_cnt = 0, g_done = 0;
__device__ float  g_mean0 = 0.f, g_mean1 = 0.f;

// Pass 1: per-ray sphere intersection; reduce sum(si0), sum(si1), count over hits.
// Last block finalizes float means and resets the accumulators for the next replay.
__global__ __launch_bounds__(256) void k_reduce(const float* __restrict__ rd,
                                                const float* __restrict__ cam, int P) {
    int i = blockIdx.x * blockDim.x + threadIdx.x;
    float cx = cam[0], cy = cam[1], cz = cam[2];
    float c2 = cx * cx + cy * cy + cz * cz - 1.0f;  // R_SPHERE = 1
    float s0 = 0.f, s1 = 0.f; int c = 0;
    if (i < P) {
        float x = rd[3 * i + 0], y = rd[3 * i + 1], z = rd[3 * i + 2];
        float dt = x * cx + y * cy + z * cz;
        float un = dt * dt - c2;
        if (un > 0.f) {
            float sq = sqrtf(un);
            s0 = -sq - dt; s1 = sq - dt; c = 1;
        }
    }
    #pragma unroll
    for (int d = 16; d; d >>= 1) {
        s0 += __shfl_down_sync(FULL, s0, d);
        s1 += __shfl_down_sync(FULL, s1, d);
        c  += __shfl_down_sync(FULL, c, d);
    }
    __shared__ float sh0[8], sh1[8]; __shared__ int shc[8];
    int w = threadIdx.x >> 5, ln = threadIdx.x & 31;
    if (ln == 0) { sh0[w] = s0; sh1[w] = s1; shc[w] = c; }
    __syncthreads();
    if (threadIdx.x == 0) {
        float a0 = 0.f, a1 = 0.f; int ac = 0;
        #pragma unroll
        for (int j = 0; j < 8; j++) { a0 += sh0[j]; a1 += sh1[j]; ac += shc[j]; }
        atomicAdd(&g_sum0, (double)a0);
        atomicAdd(&g_sum1, (double)a1);
        atomicAdd(&g_cnt, ac);
        __threadfence();
        int t = atomicAdd(&g_done, 1);
        if (t == (int)gridDim.x - 1) {
            double t0 = atomicAdd(&g_sum0, 0.0);
            double t1 = atomicAdd(&g_sum1, 0.0);
            int    nc = atomicAdd(&g_cnt, 0);
            int nh = nc > 0 ? nc : 1;
            g_mean0 = (float)(t0 / (double)nh);   // one FP64 divide per launch
            g_mean1 = (float)(t1 / (double)nh);
            __threadfence();
            // reset for next graph replay
            g_sum0 = 0.0; g_sum1 = 0.0; g_cnt = 0; g_done = 0;
        }
    }
}

// Pass 2: one warp per ray. Lane l owns steps {2l, 2l+1}.
__global__ __launch_bounds__(256) void k_main(const float* __restrict__ rd,
                                              const float* __restrict__ cam,
                                              const float* __restrict__ trand,
                                              float* __restrict__ ns,
                                              float* __restrict__ zs,
                                              float* __restrict__ wout, int P) {
    __shared__ float2 scum[8][32];   // per-warp cum[64] as float2 per lane
    __shared__ float2 sstp[8][32];   // per-warp steps[64]

    int gt   = blockIdx.x * blockDim.x + threadIdx.x;
    int ray  = gt >> 5;
    int lane = gt & 31;
    int wid  = (threadIdx.x >> 5);
    if (ray >= P) return;

    float cx = cam[0], cy = cam[1], cz = cam[2];
    float c2 = cx * cx + cy * cy + cz * cz - 1.0f;
    float x = rd[3 * ray + 0], y = rd[3 * ray + 1], z = rd[3 * ray + 2];
    float dt = x * cx + y * cy + z * cz;
    float un = dt * dt - c2;

    float si0, si1;
    if (un > 0.f) {
        float sq = sqrtf(un);
        si0 = -sq - dt; si1 = sq - dt;
    } else {
        si0 = g_mean0;
        si1 = g_mean1;
    }
    si0 = fmaxf(si0, 0.f); si1 = fmaxf(si1, 0.f);
    float mind = si0;
    float rng  = si1 - si0;
    float sd   = rng * (1.0f / 64.0f);

    // steps (coalesced float2 load of t_rand)
    float2 tr = *(const float2*)(trand + (size_t)ray * 64 + 2 * lane);
    int i0 = 2 * lane, i1 = 2 * lane + 1;
    float st0 = mind + ((float)i0 * (1.0f / 63.0f)) * rng + (tr.x - 0.5f) * sd;
    float st1 = mind + ((float)i1 * (1.0f / 63.0f)) * rng + (tr.y - 0.5f) * sd;

    // SDF at both steps
    float px = cx + st0 * x, py = cy + st0 * y, pz = cz + st0 * z;
    float s_0 = sqrtf(px * px + py * py + pz * pz) - 0.5f;
    px = cx + st1 * x; py = cy + st1 * y; pz = cz + st1 * z;
    float s_1 = sqrtf(px * px + py * py + pz * pz) - 0.5f;

    const float inv_s = 20.085536923187668f;  // exp(0.3 * 10)
    float sg0 = 1.0f / (1.0f + __expf(-s_0 * inv_s));
    float sg1 = 1.0f / (1.0f + __expf(-s_1 * inv_s));
    float sgn = __shfl_down_sync(FULL, sg0, 1);   // sigmoid(sdf[2l+2]) from next lane

    float a0 = fminf(fmaxf(__fdividef(sg0 - sg1 + 1e-8f, sg0 + 1e-8f), 0.f), 1.f);
    float a1 = (lane < 31)
             ? fminf(fmaxf(__fdividef(sg1 - sgn + 1e-8f, sg1 + 1e-8f), 0.f), 1.f)
             : 0.f;

    float g0 = 1.0f - a0 + 1e-7f;
    float g1 = (lane < 31) ? (1.0f - a1 + 1e-7f) : 1.0f;

    // exclusive prefix-product across warp of per-lane pair product
    float pi = g0 * g1;
    #pragma unroll
    for (int d = 1; d < 32; d <<= 1) {
        float v = __shfl_up_sync(FULL, pi, d);
        if (lane >= d) pi *= v;
    }
    float Pex = __shfl_up_sync(FULL, pi, 1);
    if (lane == 0) Pex = 1.0f;

    float w0 = a0 * Pex;            // weights[2l]
    float w1 = a1 * (Pex * g0);     // weights[2l+1] (unused for lane 31)

    // unnormalized CDF (cumsum of w + 1e-8); index 63 padded with 0 contribution
    float e0 = w0 + 1e-8f;
    float e1 = (lane < 31) ? (w1 + 1e-8f) : 0.f;
    float qi = e0 + e1;
    #pragma unroll
    for (int d = 1; d < 32; d <<= 1) {
        float v = __shfl_up_sync(FULL, qi, d);
        if (lane >= d) qi += v;
    }
    float Sex = __shfl_up_sync(FULL, qi, 1);
    if (lane == 0) Sex = 0.f;
    float cum0  = Sex + e0;   // cumw[2l]
    float cum1  = qi;         // cumw[2l+1]
    float total = __shfl_sync(FULL, qi, 31);

    // stash cum + steps in smem for the binary search (replaces shuffle gathers)
    scum[wid][lane] = make_float2(cum0, cum1);
    sstp[wid][lane] = make_float2(st0, st1);
    __syncwarp();
    const float* cumA = (const float*)scum[wid];
    const float* stpA = (const float*)sstp[wid];

    // write weights (63 per ray)
    size_t wbase = (size_t)ray * 63;
    wout[wbase + i0] = w0;
    if (lane < 31) wout[wbase + i1] = w1;

    // importance sample: one u per lane, u = (2l+1)/64
    float u  = (float)(2 * lane + 1) * (1.0f / 64.0f);
    float uT = u * total;

    // c = count of cumw[k] <= uT over k in [0,63)
    int c = 0;
    #pragma unroll
    for (int s = 32; s; s >>= 1) {
        int k = c + s - 1;
        if (k < 63 && cumA[k] <= uT) c += s;
    }
    int   ab   = min(c + 1, 63);
    float rtot = __frcp_rn(total);
    float cdfb = (c == 0) ? 0.f : cumA[c - 1] * rtot;
    float cdfa = cumA[ab - 1] * rtot;
    float binb = stpA[c];
    float bina = stpA[ab];
    float den  = cdfa - cdfb;
    den = (den < 1e-8f) ? 1.0f : den;
    float zv = binb + __fdividef(u - cdfb, den) * (bina - binb);

    // z_samples (coalesced)
    zs[(size_t)ray * 32 + lane] = zv;

    // new_samples: 96 contiguous floats per warp, written as 3 coalesced STGs.
    // Element e = 32*j + lane belongs to sample s=e/3, component cmp=e%3;
    // zv for sample s lives in lane s (shuffle), dir/cam components are warp-uniform.
    size_t nbase = (size_t)ray * 96;
    #pragma unroll
    for (int j = 0; j < 3; j++) {
        int e   = 32 * j + lane;
        int s   = e / 3;
        int cmp = e - 3 * s;
        float zval = __shfl_sync(FULL, zv, s);
        float dirc = (cmp == 0) ? x  : (cmp == 1) ? y  : z;
        float camc = (cmp == 0) ? cx : (cmp == 1) ? cy : cz;
        ns[nbase + e] = camc + zval * dirc;
    }
}

extern "C" void kernel_launch(void* const* d_in, const int* in_sizes, int n_in,
                              void* d_out, int out_size) {
    const float* rd  = (const float*)d_in[0];   // ray_dirs (1, P, 3)
    const float* cam = (const float*)d_in[1];   // cam_loc (1, 3)
    const float* tr  = (const float*)d_in[2];   // t_rand (P, 64)
    int P = in_sizes[0] / 3;

    float* out = (float*)d_out;
    float* ns  = out;                                     // (P, 32, 3)
    float* zs  = out + (size_t)P * 96;                    // (P, 32)
    float* wo  = out + (size_t)P * 96 + (size_t)P * 32;   // (P, 63)

    k_reduce<<<(P + 255) / 256, 256>>>(rd, cam, P);
    long long tot = (long long)P * 32;
    k_main<<<(int)((tot + 255) / 256), 256>>>(rd, cam, tr, ns, zs, wo, P);
}

// round 9
// speedup vs baseline: 5.6714x; 1.0279x over previous
#include <cuda_runtime.h>
#include <math.h>

#define FULL 0xffffffffu

// Global-reduction scratch. Statically zero; the k_reduce finalizer resets it
// after use so every graph replay sees the same initial state.
__device__ double g_sum0 = 0.0, g_sum1 = 0.0;
__device__ int    g_cnt = 0, g_done = 0;
__device__ float  g_mean0 = 0.f, g_mean1 = 0.f;

// Pass 1: 4 rays/thread, float4 loads. Reduce sum(si0), sum(si1), hit count.
__global__ __launch_bounds__(256) void k_reduce(const float* __restrict__ rd,
                                                const float* __restrict__ cam, int P) {
    int i = (blockIdx.x * blockDim.x + threadIdx.x) * 4;
    float cx = cam[0], cy = cam[1], cz = cam[2];
    float c2 = cx * cx + cy * cy + cz * cz - 1.0f;  // R_SPHERE = 1
    float s0 = 0.f, s1 = 0.f; int c = 0;
    if (i + 3 < P) {
        const float4* p4 = (const float4*)(rd + 3 * i);   // 48B-aligned (16 | 48i)
        float4 v0 = p4[0], v1 = p4[1], v2 = p4[2];
        float f[12] = {v0.x, v0.y, v0.z, v0.w, v1.x, v1.y, v1.z, v1.w,
                       v2.x, v2.y, v2.z, v2.w};
        #pragma unroll
        for (int r = 0; r < 4; r++) {
            float dt = f[3*r] * cx + f[3*r+1] * cy + f[3*r+2] * cz;
            float un = dt * dt - c2;
            if (un > 0.f) {
                float sq = sqrtf(un);
                s0 += -sq - dt; s1 += sq - dt; c++;
            }
        }
    } else {
        for (int r = 0; r < 4 && i + r < P; r++) {
            int ii = i + r;
            float dt = rd[3*ii] * cx + rd[3*ii+1] * cy + rd[3*ii+2] * cz;
            float un = dt * dt - c2;
            if (un > 0.f) {
                float sq = sqrtf(un);
                s0 += -sq - dt; s1 += sq - dt; c++;
            }
        }
    }
    #pragma unroll
    for (int d = 16; d; d >>= 1) {
        s0 += __shfl_down_sync(FULL, s0, d);
        s1 += __shfl_down_sync(FULL, s1, d);
        c  += __shfl_down_sync(FULL, c, d);
    }
    __shared__ float sh0[8], sh1[8]; __shared__ int shc[8];
    int w = threadIdx.x >> 5, ln = threadIdx.x & 31;
    if (ln == 0) { sh0[w] = s0; sh1[w] = s1; shc[w] = c; }
    __syncthreads();
    if (threadIdx.x == 0) {
        float a0 = 0.f, a1 = 0.f; int ac = 0;
        #pragma unroll
        for (int j = 0; j < 8; j++) { a0 += sh0[j]; a1 += sh1[j]; ac += shc[j]; }
        atomicAdd(&g_sum0, (double)a0);
        atomicAdd(&g_sum1, (double)a1);
        atomicAdd(&g_cnt, ac);
        __threadfence();
        int t = atomicAdd(&g_done, 1);
        if (t == (int)gridDim.x - 1) {
            double t0 = atomicAdd(&g_sum0, 0.0);
            double t1 = atomicAdd(&g_sum1, 0.0);
            int    nc = atomicAdd(&g_cnt, 0);
            int nh = nc > 0 ? nc : 1;
            g_mean0 = (float)(t0 / (double)nh);
            g_mean1 = (float)(t1 / (double)nh);
            __threadfence();
            g_sum0 = 0.0; g_sum1 = 0.0; g_cnt = 0; g_done = 0;  // reset for next replay
        }
    }
}

// Pass 2: one warp per ray. Lane l owns steps {2l, 2l+1}.
__global__ __launch_bounds__(256) void k_main(const float* __restrict__ rd,
                                              const float* __restrict__ cam,
                                              const float* __restrict__ trand,
                                              float* __restrict__ ns,
                                              float* __restrict__ zs,
                                              float* __restrict__ wout, int P) {
    __shared__ float2 scum[8][32];   // per-warp cum[64] (2/lane)
    __shared__ float2 sstp[8][32];   // per-warp steps[64]
    __shared__ float4 sns[8][32];    // per-warp new_samples staging (padded 3->4)

    int gt   = blockIdx.x * blockDim.x + threadIdx.x;
    int ray  = gt >> 5;
    int lane = gt & 31;
    int wid  = (threadIdx.x >> 5);
    if (ray >= P) return;

    float cx = cam[0], cy = cam[1], cz = cam[2];
    float c2 = cx * cx + cy * cy + cz * cz - 1.0f;
    float x = rd[3 * ray + 0], y = rd[3 * ray + 1], z = rd[3 * ray + 2];
    float dt = x * cx + y * cy + z * cz;
    float un = dt * dt - c2;

    float si0, si1;
    if (un > 0.f) {
        float sq = sqrtf(un);
        si0 = -sq - dt; si1 = sq - dt;
    } else {
        si0 = g_mean0;
        si1 = g_mean1;
    }
    si0 = fmaxf(si0, 0.f); si1 = fmaxf(si1, 0.f);
    float mind = si0;
    float rng  = si1 - si0;
    float sd   = rng * (1.0f / 64.0f);

    // steps (coalesced float2 load of t_rand)
    float2 tr = *(const float2*)(trand + (unsigned)ray * 64u + 2u * (unsigned)lane);
    int i0 = 2 * lane, i1 = 2 * lane + 1;
    float st0 = mind + ((float)i0 * (1.0f / 63.0f)) * rng + (tr.x - 0.5f) * sd;
    float st1 = mind + ((float)i1 * (1.0f / 63.0f)) * rng + (tr.y - 0.5f) * sd;

    // SDF at both steps
    float px = cx + st0 * x, py = cy + st0 * y, pz = cz + st0 * z;
    float s_0 = sqrtf(px * px + py * py + pz * pz) - 0.5f;
    px = cx + st1 * x; py = cy + st1 * y; pz = cz + st1 * z;
    float s_1 = sqrtf(px * px + py * py + pz * pz) - 0.5f;

    const float inv_s = 20.085536923187668f;  // exp(0.3 * 10)
    float sg0 = 1.0f / (1.0f + __expf(-s_0 * inv_s));
    float sg1 = 1.0f / (1.0f + __expf(-s_1 * inv_s));
    float sgn = __shfl_down_sync(FULL, sg0, 1);   // sigmoid(sdf[2l+2])

    float a0 = fminf(fmaxf(__fdividef(sg0 - sg1 + 1e-8f, sg0 + 1e-8f), 0.f), 1.f);
    float a1 = (lane < 31)
             ? fminf(fmaxf(__fdividef(sg1 - sgn + 1e-8f, sg1 + 1e-8f), 0.f), 1.f)
             : 0.f;

    float g0 = 1.0f - a0 + 1e-7f;
    float g1 = (lane < 31) ? (1.0f - a1 + 1e-7f) : 1.0f;

    // exclusive prefix-product across warp of per-lane pair product
    float pi = g0 * g1;
    #pragma unroll
    for (int d = 1; d < 32; d <<= 1) {
        float v = __shfl_up_sync(FULL, pi, d);
        if (lane >= d) pi *= v;
    }
    float Pex = __shfl_up_sync(FULL, pi, 1);
    if (lane == 0) Pex = 1.0f;

    float w0 = a0 * Pex;            // weights[2l]
    float w1 = a1 * (Pex * g0);     // weights[2l+1] (unused for lane 31)

    // unnormalized CDF (cumsum of w + 1e-8); element 63 contributes 0
    float e0 = w0 + 1e-8f;
    float e1 = (lane < 31) ? (w1 + 1e-8f) : 0.f;
    float qi = e0 + e1;
    #pragma unroll
    for (int d = 1; d < 32; d <<= 1) {
        float v = __shfl_up_sync(FULL, qi, d);
        if (lane >= d) qi += v;
    }
    float Sex = __shfl_up_sync(FULL, qi, 1);
    if (lane == 0) Sex = 0.f;
    float cum0  = Sex + e0;   // cumw[2l]
    float cum1  = qi;         // cumw[2l+1]
    float total = __shfl_sync(FULL, qi, 31);

    // stash cum + steps in smem for the search
    scum[wid][lane] = make_float2(cum0, cum1);
    sstp[wid][lane] = make_float2(st0, st1);
    __syncwarp();
    const float* cumA = (const float*)scum[wid];
    const float* stpA = (const float*)sstp[wid];

    // write weights (63 per ray)
    unsigned wbase = (unsigned)ray * 63u;
    wout[wbase + i0] = w0;
    if (lane < 31) wout[wbase + i1] = w1;

    // importance sample: one u per lane, u = (2l+1)/64
    float u  = (float)(2 * lane + 1) * (1.0f / 64.0f);
    float uT = u * total;

    // c = count of cumw[k] <= uT over k in [0,63).
    // k = c+s-1 never exceeds 62 across iterations (worst chain 31,47,55,59,61,62),
    // so no bounds guard is needed.
    int c = 0;
    #pragma unroll
    for (int s = 32; s; s >>= 1) {
        if (cumA[c + s - 1] <= uT) c += s;
    }
    int   ab   = min(c + 1, 63);
    float rtot = __frcp_rn(total);
    float cdfb = (c == 0) ? 0.f : cumA[c - 1] * rtot;
    float cdfa = cumA[ab - 1] * rtot;
    float binb = stpA[c];
    float bina = stpA[ab];
    float den  = cdfa - cdfb;
    den = (den < 1e-8f) ? 1.0f : den;
    float zv = binb + __fdividef(u - cdfb, den) * (bina - binb);

    // z_samples (coalesced)
    zs[(unsigned)ray * 32u + (unsigned)lane] = zv;

    // new_samples: lane computes its own sample's coords, stage padded-4 in smem,
    // then 3 coalesced 128B stores. packed idx e -> padded idx e + e/3.
    float nx = fmaf(zv, x, cx);
    float ny = fmaf(zv, y, cy);
    float nz = fmaf(zv, z, cz);
    sns[wid][lane] = make_float4(nx, ny, nz, 0.f);
    __syncwarp();
    const float* nsrc = (const float*)sns[wid];
    unsigned nbase = (unsigned)ray * 96u;
    #pragma unroll
    for (int j = 0; j < 3; j++) {
        int e = 32 * j + lane;
        ns[nbase + e] = nsrc[e + e / 3];
    }
}

extern "C" void kernel_launch(void* const* d_in, const int* in_sizes, int n_in,
                              void* d_out, int out_size) {
    const float* rd  = (const float*)d_in[0];   // ray_dirs (1, P, 3)
    const float* cam = (const float*)d_in[1];   // cam_loc (1, 3)
    const float* tr  = (const float*)d_in[2];   // t_rand (P, 64)
    int P = in_sizes[0] / 3;

    float* out = (float*)d_out;
    float* ns  = out;                                     // (P, 32, 3)
    float* zs  = out + (size_t)P * 96;                    // (P, 32)
    float* wo  = out + (size_t)P * 96 + (size_t)P * 32;   // (P, 63)

    int rblocks = (P + 1023) / 1024;                      // 4 rays/thread
    k_reduce<<<rblocks, 256>>>(rd, cam, P);
    long long tot = (long long)P * 32;
    k_main<<<(int)((tot + 255) / 256), 256>>>(rd, cam, tr, ns, zs, wo, P);
}

// round 10
// speedup vs baseline: 6.0022x; 1.0583x over previous
#include <cuda_runtime.h>
#include <math.h>

#define FULL 0xffffffffu

// Guaranteed single-MUFU approx ops (independent of compiler fast-math flags).
__device__ __forceinline__ float fast_sqrt(float x) {
    float r; asm("sqrt.approx.f32 %0, %1;" : "=f"(r) : "f"(x)); return r;
}
__device__ __forceinline__ float fast_rcp(float x) {
    float r; asm("rcp.approx.f32 %0, %1;" : "=f"(r) : "f"(x)); return r;
}

// Global-reduction scratch. Statically zero; the k_reduce finalizer resets it
// after use so every graph replay sees the same initial state.
__device__ double g_sum0 = 0.0, g_sum1 = 0.0;
__device__ int    g_cnt = 0, g_done = 0;
__device__ float  g_mean0 = 0.f, g_mean1 = 0.f;

// Pass 1: 4 rays/thread, float4 loads. Reduce sum(si0), sum(si1), hit count.
__global__ __launch_bounds__(256) void k_reduce(const float* __restrict__ rd,
                                                const float* __restrict__ cam, int P) {
    int i = (blockIdx.x * blockDim.x + threadIdx.x) * 4;
    float cx = cam[0], cy = cam[1], cz = cam[2];
    float c2 = cx * cx + cy * cy + cz * cz - 1.0f;  // R_SPHERE = 1
    float s0 = 0.f, s1 = 0.f; int c = 0;
    if (i + 3 < P) {
        const float4* p4 = (const float4*)(rd + 3 * i);   // 48B-aligned (16 | 48i)
        float4 v0 = p4[0], v1 = p4[1], v2 = p4[2];
        float f[12] = {v0.x, v0.y, v0.z, v0.w, v1.x, v1.y, v1.z, v1.w,
                       v2.x, v2.y, v2.z, v2.w};
        #pragma unroll
        for (int r = 0; r < 4; r++) {
            float dt = f[3*r] * cx + f[3*r+1] * cy + f[3*r+2] * cz;
            float un = dt * dt - c2;
            if (un > 0.f) {
                float sq = fast_sqrt(un);
                s0 += -sq - dt; s1 += sq - dt; c++;
            }
        }
    } else {
        for (int r = 0; r < 4 && i + r < P; r++) {
            int ii = i + r;
            float dt = rd[3*ii] * cx + rd[3*ii+1] * cy + rd[3*ii+2] * cz;
            float un = dt * dt - c2;
            if (un > 0.f) {
                float sq = fast_sqrt(un);
                s0 += -sq - dt; s1 += sq - dt; c++;
            }
        }
    }
    #pragma unroll
    for (int d = 16; d; d >>= 1) {
        s0 += __shfl_down_sync(FULL, s0, d);
        s1 += __shfl_down_sync(FULL, s1, d);
        c  += __shfl_down_sync(FULL, c, d);
    }
    __shared__ float sh0[8], sh1[8]; __shared__ int shc[8];
    int w = threadIdx.x >> 5, ln = threadIdx.x & 31;
    if (ln == 0) { sh0[w] = s0; sh1[w] = s1; shc[w] = c; }
    __syncthreads();
    if (threadIdx.x == 0) {
        float a0 = 0.f, a1 = 0.f; int ac = 0;
        #pragma unroll
        for (int j = 0; j < 8; j++) { a0 += sh0[j]; a1 += sh1[j]; ac += shc[j]; }
        atomicAdd(&g_sum0, (double)a0);
        atomicAdd(&g_sum1, (double)a1);
        atomicAdd(&g_cnt, ac);
        __threadfence();
        int t = atomicAdd(&g_done, 1);
        if (t == (int)gridDim.x - 1) {
            double t0 = atomicAdd(&g_sum0, 0.0);
            double t1 = atomicAdd(&g_sum1, 0.0);
            int    nc = atomicAdd(&g_cnt, 0);
            int nh = nc > 0 ? nc : 1;
            g_mean0 = (float)(t0 / (double)nh);
            g_mean1 = (float)(t1 / (double)nh);
            __threadfence();
            g_sum0 = 0.0; g_sum1 = 0.0; g_cnt = 0; g_done = 0;  // reset for next replay
        }
    }
}

// Pass 2: one warp per ray. Lane l owns steps {2l, 2l+1}.
__global__ __launch_bounds__(256) void k_main(const float* __restrict__ rd,
                                              const float* __restrict__ cam,
                                              const float* __restrict__ trand,
                                              float* __restrict__ ns,
                                              float* __restrict__ zs,
                                              float* __restrict__ wout, int P) {
    __shared__ float2 scum[8][32];   // per-warp cum[64] (2/lane)
    __shared__ float2 sstp[8][32];   // per-warp steps[64]
    __shared__ float4 sns[8][32];    // per-warp new_samples staging (padded 3->4)

    int gt   = blockIdx.x * blockDim.x + threadIdx.x;
    int ray  = gt >> 5;
    int lane = gt & 31;
    int wid  = (threadIdx.x >> 5);
    if (ray >= P) return;

    float cx = cam[0], cy = cam[1], cz = cam[2];
    float c2 = cx * cx + cy * cy + cz * cz - 1.0f;
    float x = rd[3 * ray + 0], y = rd[3 * ray + 1], z = rd[3 * ray + 2];
    float dt = x * cx + y * cy + z * cz;
    float un = dt * dt - c2;

    float si0, si1;
    if (un > 0.f) {
        float sq = fast_sqrt(un);
        si0 = -sq - dt; si1 = sq - dt;
    } else {
        si0 = g_mean0;
        si1 = g_mean1;
    }
    si0 = fmaxf(si0, 0.f); si1 = fmaxf(si1, 0.f);
    float mind = si0;
    float rng  = si1 - si0;
    float sd   = rng * (1.0f / 64.0f);

    // steps (coalesced float2 load of t_rand)
    float2 tr = *(const float2*)(trand + (unsigned)ray * 64u + 2u * (unsigned)lane);
    int i0 = 2 * lane, i1 = 2 * lane + 1;
    float st0 = mind + ((float)i0 * (1.0f / 63.0f)) * rng + (tr.x - 0.5f) * sd;
    float st1 = mind + ((float)i1 * (1.0f / 63.0f)) * rng + (tr.y - 0.5f) * sd;

    // SDF at both steps
    float px = cx + st0 * x, py = cy + st0 * y, pz = cz + st0 * z;
    float s_0 = fast_sqrt(px * px + py * py + pz * pz) - 0.5f;
    px = cx + st1 * x; py = cy + st1 * y; pz = cz + st1 * z;
    float s_1 = fast_sqrt(px * px + py * py + pz * pz) - 0.5f;

    const float inv_s = 20.085536923187668f;  // exp(0.3 * 10)
    float sg0 = fast_rcp(1.0f + __expf(-s_0 * inv_s));
    float sg1 = fast_rcp(1.0f + __expf(-s_1 * inv_s));
    float sgn = __shfl_down_sync(FULL, sg0, 1);   // sigmoid(sdf[2l+2])

    float a0 = fminf(fmaxf(__fdividef(sg0 - sg1 + 1e-8f, sg0 + 1e-8f), 0.f), 1.f);
    float a1 = (lane < 31)
             ? fminf(fmaxf(__fdividef(sg1 - sgn + 1e-8f, sg1 + 1e-8f), 0.f), 1.f)
             : 0.f;

    float g0 = 1.0f - a0 + 1e-7f;
    float g1 = (lane < 31) ? (1.0f - a1 + 1e-7f) : 1.0f;

    // exclusive prefix-product across warp of per-lane pair product
    float pi = g0 * g1;
    #pragma unroll
    for (int d = 1; d < 32; d <<= 1) {
        float v = __shfl_up_sync(FULL, pi, d);
        if (lane >= d) pi *= v;
    }
    float Pex = __shfl_up_sync(FULL, pi, 1);
    if (lane == 0) Pex = 1.0f;

    float w0 = a0 * Pex;            // weights[2l]
    float w1 = a1 * (Pex * g0);     // weights[2l+1] (unused for lane 31)

    // unnormalized CDF (cumsum of w + 1e-8); element 63 contributes 0
    float e0 = w0 + 1e-8f;
    float e1 = (lane < 31) ? (w1 + 1e-8f) : 0.f;
    float qi = e0 + e1;
    #pragma unroll
    for (int d = 1; d < 32; d <<= 1) {
        float v = __shfl_up_sync(FULL, qi, d);
        if (lane >= d) qi += v;
    }
    float Sex = __shfl_up_sync(FULL, qi, 1);
    if (lane == 0) Sex = 0.f;
    float cum0  = Sex + e0;   // cumw[2l]
    float cum1  = qi;         // cumw[2l+1]
    float total = __shfl_sync(FULL, qi, 31);

    // stash cum + steps in smem for the search
    scum[wid][lane] = make_float2(cum0, cum1);
    sstp[wid][lane] = make_float2(st0, st1);
    __syncwarp();
    const float* cumA = (const float*)scum[wid];
    const float* stpA = (const float*)sstp[wid];

    // write weights (63 per ray)
    unsigned wbase = (unsigned)ray * 63u;
    wout[wbase + i0] = w0;
    if (lane < 31) wout[wbase + i1] = w1;

    // importance sample: one u per lane, u = (2l+1)/64
    float u  = (float)(2 * lane + 1) * (1.0f / 64.0f);
    float uT = u * total;

    // c = count of cumw[k] <= uT over k in [0,63).
    // k = c+s-1 never exceeds 62 across iterations (worst chain 31,47,55,59,61,62),
    // so no bounds guard is needed.
    int c = 0;
    #pragma unroll
    for (int s = 32; s; s >>= 1) {
        if (cumA[c + s - 1] <= uT) c += s;
    }
    int   ab   = min(c + 1, 63);
    float rtot = fast_rcp(total);
    float cdfb = (c == 0) ? 0.f : cumA[c - 1] * rtot;
    float cdfa = cumA[ab - 1] * rtot;
    float binb = stpA[c];
    float bina = stpA[ab];
    float den  = cdfa - cdfb;
    den = (den < 1e-8f) ? 1.0f : den;
    float zv = binb + __fdividef(u - cdfb, den) * (bina - binb);

    // z_samples (coalesced)
    zs[(unsigned)ray * 32u + (unsigned)lane] = zv;

    // new_samples: lane computes its own sample's coords, stage padded-4 in smem,
    // then 3 coalesced 128B stores. packed idx e -> padded idx e + e/3.
    float nx = fmaf(zv, x, cx);
    float ny = fmaf(zv, y, cy);
    float nz = fmaf(zv, z, cz);
    sns[wid][lane] = make_float4(nx, ny, nz, 0.f);
    __syncwarp();
    const float* nsrc = (const float*)sns[wid];
    unsigned nbase = (unsigned)ray * 96u;
    #pragma unroll
    for (int j = 0; j < 3; j++) {
        int e = 32 * j + lane;
        ns[nbase + e] = nsrc[e + e / 3];
    }
}

extern "C" void kernel_launch(void* const* d_in, const int* in_sizes, int n_in,
                              void* d_out, int out_size) {
    const float* rd  = (const float*)d_in[0];   // ray_dirs (1, P, 3)
    const float* cam = (const float*)d_in[1];   // cam_loc (1, 3)
    const float* tr  = (const float*)d_in[2];   // t_rand (P, 64)
    int P = in_sizes[0] / 3;

    float* out = (float*)d_out;
    float* ns  = out;                                     // (P, 32, 3)
    float* zs  = out + (size_t)P * 96;                    // (P, 32)
    float* wo  = out + (size_t)P * 96 + (size_t)P * 32;   // (P, 63)

    int rblocks = (P + 1023) / 1024;                      // 4 rays/thread
    k_reduce<<<rblocks, 256>>>(rd, cam, P);
    long long tot = (long long)P * 32;
    k_main<<<(int)((tot + 255) / 256), 256>>>(rd, cam, tr, ns, zs, wo, P);
}